// round 2
// baseline (speedup 1.0000x reference)
#include <cuda_runtime.h>
#include <cstdint>

#define S_LEN 2048
#define BATCH 32
#define IDIM  256
#define HDIM  512
#define CL    8            // cluster size (CTAs per cluster)
#define ROWS_PER_CTA 64    // HDIM / CL
#define THREADS_R 256

typedef unsigned long long ull;

// ---------------- small PTX helpers ----------------
__device__ __forceinline__ ull pack2(float x, float y) {
    ull r; asm("mov.b64 %0, {%1, %2};" : "=l"(r) : "f"(x), "f"(y)); return r;
}
__device__ __forceinline__ void unpack2(ull v, float &x, float &y) {
    asm("mov.b64 {%0, %1}, %2;" : "=f"(x), "=f"(y) : "l"(v));
}
__device__ __forceinline__ void ffma2(ull &d, ull a, ull b) {
    // packed fp32x2 fma: d.lo += a.lo*b.lo ; d.hi += a.hi*b.hi
    asm("fma.rn.f32x2 %0, %1, %2, %0;" : "+l"(d) : "l"(a), "l"(b));
}
__device__ __forceinline__ uint32_t smem_u32(const void* p) {
    return (uint32_t)__cvta_generic_to_shared(p);
}
__device__ __forceinline__ void st_cluster64(uint32_t laddr, uint32_t rank, ull v) {
    uint32_t raddr;
    asm volatile("mapa.shared::cluster.u32 %0, %1, %2;" : "=r"(raddr) : "r"(laddr), "r"(rank));
    asm volatile("st.shared::cluster.u64 [%0], %1;" :: "r"(raddr), "l"(v) : "memory");
}
__device__ __forceinline__ void cluster_sync_() {
    asm volatile("barrier.cluster.arrive.aligned;" ::: "memory");
    asm volatile("barrier.cluster.wait.aligned;"   ::: "memory");
}

// =====================================================================
// Phase 1: z[b,s,h] = inputs[b,s,:] . Wih[h,:] + bih[h] + bhh[h]
// Written in-place into d_out's [B,S,H] region.
// C[M=65536, N=512], K=256. Tiles 64x64, 256 threads, 4x4 micro-tile.
// =====================================================================
#define BM 64
#define BN 64
#define BK 32

__global__ __launch_bounds__(256) void zproj_kernel(
    const float* __restrict__ A,    // [M, 256]
    const float* __restrict__ W,    // [512, 256]
    const float* __restrict__ bih,
    const float* __restrict__ bhh,
    float* __restrict__ C)          // [M, 512]
{
    __shared__ float As[BK][BM + 4];
    __shared__ float Bs[BK][BN + 4];
    const int tid = threadIdx.x;
    const int m0 = blockIdx.x * BM;
    const int n0 = blockIdx.y * BN;
    const int tx = tid & 15;        // n micro index
    const int ty = tid >> 4;        // m micro index
    float acc[4][4] = {};

    for (int k0 = 0; k0 < IDIM; k0 += BK) {
        #pragma unroll
        for (int i = 0; i < 2; i++) {
            int s  = tid + i * 256;          // 512 slots, each a float4 along k
            int m  = s >> 3;
            int kq = (s & 7) << 2;
            float4 a = *(const float4*)(A + (size_t)(m0 + m) * IDIM + k0 + kq);
            As[kq+0][m] = a.x; As[kq+1][m] = a.y; As[kq+2][m] = a.z; As[kq+3][m] = a.w;
            float4 b = *(const float4*)(W + (size_t)(n0 + m) * IDIM + k0 + kq);
            Bs[kq+0][m] = b.x; Bs[kq+1][m] = b.y; Bs[kq+2][m] = b.z; Bs[kq+3][m] = b.w;
        }
        __syncthreads();
        #pragma unroll
        for (int k = 0; k < BK; k++) {
            float4 a4 = *(const float4*)&As[k][ty * 4];
            float4 b4 = *(const float4*)&Bs[k][tx * 4];
            float av[4] = {a4.x, a4.y, a4.z, a4.w};
            float bv[4] = {b4.x, b4.y, b4.z, b4.w};
            #pragma unroll
            for (int i = 0; i < 4; i++)
                #pragma unroll
                for (int j = 0; j < 4; j++)
                    acc[i][j] = fmaf(av[i], bv[j], acc[i][j]);
        }
        __syncthreads();
    }

    float bias[4];
    #pragma unroll
    for (int j = 0; j < 4; j++)
        bias[j] = bih[n0 + tx * 4 + j] + bhh[n0 + tx * 4 + j];

    #pragma unroll
    for (int i = 0; i < 4; i++) {
        float4 o;
        o.x = acc[i][0] + bias[0];
        o.y = acc[i][1] + bias[1];
        o.z = acc[i][2] + bias[2];
        o.w = acc[i][3] + bias[3];
        *(float4*)(C + (size_t)(m0 + ty * 4 + i) * HDIM + n0 + tx * 4) = o;
    }
}

// =====================================================================
// Phase 2: persistent cluster scan.
// Grid = 128 CTAs, cluster 8. Cluster c owns batches {2c, 2c+1}.
// CTA rank r owns output rows [64r, 64r+64) of h; its W_hh slice lives
// in registers (per thread: 2 rows x 64 k = 128 regs as 64 packed f32x2).
// h is kept per-CTA in SMEM, pre-splatted {h,h} per batch so the packed
// FFMA2 needs no MOV splats. One cluster barrier per timestep.
// =====================================================================
__global__ void __cluster_dims__(CL, 1, 1) __launch_bounds__(THREADS_R, 1)
rnn_scan_kernel(const float* __restrict__ Whh,   // [512, 512]
                const float* __restrict__ h0,    // [1, 32, 512]
                float* __restrict__ out)         // [B*S*H] z in-place -> h ; tail: h_final
{
    __shared__ __align__(16) float2 hs[2][2][HDIM];        // [buf][batch][row] = {h,h}
    __shared__ float red[2][ROWS_PER_CTA * 9];             // [batch][row*9 + kc]

    const int tid = threadIdx.x;
    const int kc  = tid >> 5;        // warp id = k-chunk, warp-uniform
    const int rp  = tid & 31;        // row pair within slice
    uint32_t rank; asm("mov.u32 %0, %%cluster_ctarank;" : "=r"(rank));
    const int cidx = blockIdx.x / CL;
    const int b0   = cidx * 2;

    // ---- load W_hh slice into registers, packed {row0, row1} per k ----
    const int grow0 = (int)rank * ROWS_PER_CTA + 2 * rp;
    const int kbase = kc * 64;
    ull w2[64];
    {
        const float* p0 = Whh + (size_t)grow0 * HDIM + kbase;
        const float* p1 = p0 + HDIM;
        #pragma unroll
        for (int jv = 0; jv < 16; jv++) {
            float4 a = *(const float4*)(p0 + 4 * jv);
            float4 b = *(const float4*)(p1 + 4 * jv);
            w2[4*jv+0] = pack2(a.x, b.x);
            w2[4*jv+1] = pack2(a.y, b.y);
            w2[4*jv+2] = pack2(a.z, b.z);
            w2[4*jv+3] = pack2(a.w, b.w);
        }
    }

    // ---- init h buffer 0 from h0 (full 512 rows, both batches, splatted) ----
    for (int g = tid; g < HDIM; g += THREADS_R) {
        float v0 = h0[(size_t)b0 * HDIM + g];
        float v1 = h0[(size_t)(b0 + 1) * HDIM + g];
        hs[0][0][g] = make_float2(v0, v0);
        hs[0][1][g] = make_float2(v1, v1);
    }

    // producer identity (threads 0..127: one (batch, row) each)
    const int pb    = tid >> 6;                    // 0/1
    const int prow  = tid & 63;
    const int pgrow = (int)rank * ROWS_PER_CTA + prow;
    size_t   zoff = 0;
    uint32_t laddr0 = 0, laddr1 = 0;
    if (tid < 128) {
        zoff   = ((size_t)(b0 + pb) * S_LEN) * HDIM + pgrow;
        laddr0 = smem_u32(&hs[0][pb][pgrow]);
        laddr1 = smem_u32(&hs[1][pb][pgrow]);
    }
    __syncthreads();

    int cur = 0;
    for (int t = 0; t < S_LEN; t++) {
        // prefetch z_t (DRAM latency hidden under the matvec)
        float zv = 0.f;
        if (tid < 128) zv = out[zoff];

        // ---- register matvec: acc over 64 k's, 2 rows x 2 batches ----
        ull acc0 = 0ull, acc1 = 0ull;   // {r0,r1} for batch0 / batch1
        const ulonglong2* s0p = (const ulonglong2*)(&hs[cur][0][kbase]);
        const ulonglong2* s1p = (const ulonglong2*)(&hs[cur][1][kbase]);
        #pragma unroll
        for (int j = 0; j < 32; j++) {
            ulonglong2 s0 = s0p[j];     // {h0[k],h0[k]} , {h0[k+1],h0[k+1]}
            ulonglong2 s1 = s1p[j];
            ffma2(acc0, w2[2*j],   s0.x);
            ffma2(acc1, w2[2*j],   s1.x);
            ffma2(acc0, w2[2*j+1], s0.y);
            ffma2(acc1, w2[2*j+1], s1.y);
        }
        float a0x, a0y, a1x, a1y;
        unpack2(acc0, a0x, a0y);
        unpack2(acc1, a1x, a1y);
        red[0][(2*rp  )*9 + kc] = a0x;
        red[0][(2*rp+1)*9 + kc] = a0y;
        red[1][(2*rp  )*9 + kc] = a1x;
        red[1][(2*rp+1)*9 + kc] = a1y;
        __syncthreads();

        if (tid < 128) {
            float s = zv;
            #pragma unroll
            for (int q = 0; q < 8; q++) s += red[pb][prow * 9 + q];
            float v = fmaxf(s, 0.f);
            out[zoff] = v;                                  // h_t overwrites z_t
            if (t == S_LEN - 1)
                out[(size_t)BATCH * S_LEN * HDIM + (size_t)(b0 + pb) * HDIM + pgrow] = v;
            ull sp = pack2(v, v);
            uint32_t la = cur ? laddr0 : laddr1;            // write next buffer
            #pragma unroll
            for (uint32_t r = 0; r < CL; r++) st_cluster64(la, r, sp);
            zoff += HDIM;
        }
        cluster_sync_();   // release pushes, acquire peers' h slices
        cur ^= 1;
    }
}

// =====================================================================
extern "C" void kernel_launch(void* const* d_in, const int* in_sizes, int n_in,
                              void* d_out, int out_size) {
    (void)in_sizes; (void)n_in; (void)out_size;
    const float* inputs = (const float*)d_in[0];
    const float* h0     = (const float*)d_in[1];
    const float* Wih    = (const float*)d_in[2];
    const float* Whh    = (const float*)d_in[3];
    const float* bih    = (const float*)d_in[4];
    const float* bhh    = (const float*)d_in[5];
    float* out = (float*)d_out;

    dim3 g1((BATCH * S_LEN) / BM, HDIM / BN);
    zproj_kernel<<<g1, 256>>>(inputs, Wih, bih, bhh, out);
    rnn_scan_kernel<<<(BATCH / 2) * CL, THREADS_R>>>(Whh, h0, out);
}

// round 6
// speedup vs baseline: 1.2018x; 1.2018x over previous
#include <cuda_runtime.h>
#include <cstdint>

#define S_LEN 2048
#define BATCH 32
#define IDIM  256
#define HDIM  512
#define CL    8            // cluster size
#define THREADS_R 256

typedef unsigned long long ull;

// ---------------- PTX helpers ----------------
__device__ __forceinline__ ull pack2(float x, float y) {
    ull r; asm("mov.b64 %0, {%1, %2};" : "=l"(r) : "f"(x), "f"(y)); return r;
}
__device__ __forceinline__ void unpack2(ull v, float &x, float &y) {
    asm("mov.b64 {%0, %1}, %2;" : "=f"(x), "=f"(y) : "l"(v));
}
__device__ __forceinline__ void ffma2(ull &d, ull a, ull b) {
    asm("fma.rn.f32x2 %0, %1, %2, %0;" : "+l"(d) : "l"(a), "l"(b));
}
__device__ __forceinline__ uint32_t smem_u32(const void* p) {
    return (uint32_t)__cvta_generic_to_shared(p);
}
__device__ __forceinline__ uint32_t mapa_addr(uint32_t laddr, uint32_t rank) {
    uint32_t raddr;
    asm("mapa.shared::cluster.u32 %0, %1, %2;" : "=r"(raddr) : "r"(laddr), "r"(rank));
    return raddr;
}
// remote store with mbarrier transaction completion (8 bytes)
__device__ __forceinline__ void st_async64(uint32_t raddr, ull v, uint32_t rmbar) {
    asm volatile("st.async.shared::cluster.mbarrier::complete_tx::bytes.b64 [%0], %1, [%2];"
                 :: "r"(raddr), "l"(v), "r"(rmbar) : "memory");
}
__device__ __forceinline__ void mbar_init(uint32_t mbar, uint32_t cnt) {
    asm volatile("mbarrier.init.shared.b64 [%0], %1;" :: "r"(mbar), "r"(cnt) : "memory");
}
__device__ __forceinline__ void mbar_arm(uint32_t mbar, uint32_t tx) {
    asm volatile("mbarrier.arrive.expect_tx.shared.b64 _, [%0], %1;" :: "r"(mbar), "r"(tx) : "memory");
}
__device__ __forceinline__ void mbar_wait(uint32_t mbar, uint32_t parity) {
    uint32_t done;
    asm volatile("{\n\t.reg .pred p;\n\t"
                 "mbarrier.try_wait.parity.acquire.cta.shared::cta.b64 p, [%1], %2;\n\t"
                 "selp.b32 %0, 1, 0, p;\n\t}"
                 : "=r"(done) : "r"(mbar), "r"(parity) : "memory");
    if (!done) {
        asm volatile("{\n\t.reg .pred P1;\n\t"
                     "WL%=:\n\t"
                     "mbarrier.try_wait.parity.acquire.cta.shared::cta.b64 P1, [%0], %1, 0x989680;\n\t"
                     "@P1 bra.uni WD%=;\n\t"
                     "bra.uni WL%=;\n\t"
                     "WD%=:\n\t}"
                     :: "r"(mbar), "r"(parity) : "memory");
    }
}
__device__ __forceinline__ void cluster_sync_() {
    asm volatile("barrier.cluster.arrive.aligned;" ::: "memory");
    asm volatile("barrier.cluster.wait.aligned;"   ::: "memory");
}

// =====================================================================
// Phase 1: z = inputs @ Wih^T + (bih + bhh), in-place into d_out.
// =====================================================================
#define BM 64
#define BN 64
#define BK 32

__global__ __launch_bounds__(256) void zproj_kernel(
    const float* __restrict__ A, const float* __restrict__ W,
    const float* __restrict__ bih, const float* __restrict__ bhh,
    float* __restrict__ C)
{
    __shared__ float As[BK][BM + 4];
    __shared__ float Bs[BK][BN + 4];
    const int tid = threadIdx.x;
    const int m0 = blockIdx.x * BM;
    const int n0 = blockIdx.y * BN;
    const int tx = tid & 15;
    const int ty = tid >> 4;
    float acc[4][4] = {};

    for (int k0 = 0; k0 < IDIM; k0 += BK) {
        #pragma unroll
        for (int i = 0; i < 2; i++) {
            int s  = tid + i * 256;
            int m  = s >> 3;
            int kq = (s & 7) << 2;
            float4 a = *(const float4*)(A + (size_t)(m0 + m) * IDIM + k0 + kq);
            As[kq+0][m] = a.x; As[kq+1][m] = a.y; As[kq+2][m] = a.z; As[kq+3][m] = a.w;
            float4 b = *(const float4*)(W + (size_t)(n0 + m) * IDIM + k0 + kq);
            Bs[kq+0][m] = b.x; Bs[kq+1][m] = b.y; Bs[kq+2][m] = b.z; Bs[kq+3][m] = b.w;
        }
        __syncthreads();
        #pragma unroll
        for (int k = 0; k < BK; k++) {
            float4 a4 = *(const float4*)&As[k][ty * 4];
            float4 b4 = *(const float4*)&Bs[k][tx * 4];
            float av[4] = {a4.x, a4.y, a4.z, a4.w};
            float bv[4] = {b4.x, b4.y, b4.z, b4.w};
            #pragma unroll
            for (int i = 0; i < 4; i++)
                #pragma unroll
                for (int j = 0; j < 4; j++)
                    acc[i][j] = fmaf(av[i], bv[j], acc[i][j]);
        }
        __syncthreads();
    }

    float bias[4];
    #pragma unroll
    for (int j = 0; j < 4; j++)
        bias[j] = bih[n0 + tx * 4 + j] + bhh[n0 + tx * 4 + j];

    #pragma unroll
    for (int i = 0; i < 4; i++) {
        float4 o;
        o.x = acc[i][0] + bias[0];
        o.y = acc[i][1] + bias[1];
        o.z = acc[i][2] + bias[2];
        o.w = acc[i][3] + bias[3];
        *(float4*)(C + (size_t)(m0 + ty * 4 + i) * HDIM + n0 + tx * 4) = o;
    }
}

// =====================================================================
// Phase 2: persistent cluster scan, st.async + mbarrier sync.
// 16 clusters x 8 CTAs. Cluster owns 2 batches; CTA rank r owns rows
// [64r, 64r+64). Thread (warp w, lane l): rowpair rpL = 4w + (l>>3),
// k-chunk kc = l&7 (64 k's). W held in regs as k-pair packed f32x2.
// h in smem as padded float2 slots; shfl-bfly reduce over 8 kc lanes;
// lanes kc<2 publish rows {2rpL, 2rpL+1} for batch kc via st.async to
// all 8 ranks. No __syncthreads / cluster barrier in the loop.
// =====================================================================
#define NSLOT 264   // 256 kpair slots + 8 pad (1 per 32)
#define TX_PER_STEP 4096u   // 8 CTAs * 64 pushers * 8B

__global__ void __cluster_dims__(CL, 1, 1) __launch_bounds__(THREADS_R, 1)
rnn_scan_kernel(const float* __restrict__ Whh,
                const float* __restrict__ h0,
                float* __restrict__ out)
{
    __shared__ __align__(16) float2 hs[2][2][NSLOT];   // [buf][batch][slot]
    __shared__ __align__(8)  ull mbarS[2];

    const int tid = threadIdx.x;
    const int w   = tid >> 5;
    const int l   = tid & 31;
    const int kc  = l & 7;
    const int rp4 = l >> 3;
    const int rpL = w * 4 + rp4;          // CTA-local rowpair 0..31
    uint32_t rank; asm("mov.u32 %0, %%cluster_ctarank;" : "=r"(rank));
    const int b0 = (blockIdx.x / CL) * 2;

    const uint32_t m0a = smem_u32(&mbarS[0]);
    const uint32_t m1a = smem_u32(&mbarS[1]);

    // ---- W slice into regs: rows {2rpL, 2rpL+1}, k in [kc*64, kc*64+64) ----
    const int grow = (int)rank * 64 + 2 * rpL;
    const ull* wr0 = (const ull*)(Whh + (size_t)grow * HDIM + kc * 64);
    const ull* wr1 = wr0 + (HDIM / 2);
    ull w2a[32], w2b[32];
    #pragma unroll
    for (int j = 0; j < 32; j++) { w2a[j] = wr0[j]; w2b[j] = wr1[j]; }

    // ---- init h buffer 0 from h0 (padded slot layout) ----
    for (int g = tid; g < HDIM; g += THREADS_R) {
        int idx = (g >> 1) + (g >> 6);
        int c = g & 1;
        ((float*)&hs[0][0][idx])[c] = h0[(size_t)b0 * HDIM + g];
        ((float*)&hs[0][1][idx])[c] = h0[(size_t)(b0 + 1) * HDIM + g];
    }
    if (tid == 0) {
        mbar_init(m0a, 1);
        mbar_init(m1a, 1);
        mbar_arm(m0a, TX_PER_STEP);   // fills during step 1 (waited at t=2)
        mbar_arm(m1a, TX_PER_STEP);   // fills during step 0 (waited at t=1)
    }
    __syncthreads();
    cluster_sync_();   // all CTAs: h0 + mbarriers ready before any st.async

    // ---- pusher setup (lanes kc<2: batch = kc, rows 2rpL, 2rpL+1) ----
    const bool pusher = (kc < 2);
    const int pb = kc;
    size_t zoff = 0, foff = 0;
    uint32_t rb[8]; uint32_t dd = 0, md0 = 0, md1 = 0;
    float2 z_cur = make_float2(0.f, 0.f);
    if (pusher) {
        zoff = ((size_t)(b0 + pb) * S_LEN) * HDIM + grow;
        foff = (size_t)BATCH * S_LEN * HDIM + (size_t)(b0 + pb) * HDIM + grow;
        int RP = (int)rank * 32 + rpL;          // global rowpair
        int slot = RP + (int)rank;              // RP + (RP>>5)
        uint32_t myslot = smem_u32(&hs[0][pb][slot]);
        #pragma unroll
        for (uint32_t r = 0; r < CL; r++) rb[r] = mapa_addr(myslot, r);
        dd  = smem_u32(&hs[1][pb][slot]) - myslot;   // buf0 -> buf1 delta
        md0 = m0a - myslot;
        md1 = m1a - myslot;
        z_cur = *(const float2*)(out + zoff);        // z[t=0] prefetch
    }

    int cur = 0;
    uint32_t p0 = 0, p1 = 0;
    for (int t = 0; t < S_LEN; t++) {
        // prefetch z_{t+1} before waiting (last iter reads in-bounds scratch)
        float2 z_next = z_cur;
        if (pusher) z_next = *(const float2*)(out + zoff + HDIM);

        if (t > 0) {
            if (cur) { mbar_wait(m1a, p1); p1 ^= 1; }
            else     { mbar_wait(m0a, p0); p0 ^= 1; }
            if (tid == 0) mbar_arm(cur ? m1a : m0a, TX_PER_STEP); // next use: fills during t+1
        }

        // ---- register matvec over this thread's 64 k's ----
        const ull* hb0 = (const ull*)&hs[cur][0][kc * 33];
        const ull* hb1 = (const ull*)&hs[cur][1][kc * 33];
        ull aA0 = 0, aA1 = 0, aB0 = 0, aB1 = 0;
        #pragma unroll
        for (int j = 0; j < 32; j++) {
            ull h0v = hb0[j];
            ull h1v = hb1[j];
            ffma2(aA0, w2a[j], h0v);   // row0, batch0
            ffma2(aA1, w2b[j], h0v);   // row1, batch0
            ffma2(aB0, w2a[j], h1v);   // row0, batch1
            ffma2(aB1, w2b[j], h1v);   // row1, batch1
        }
        float x, y, s0, s1, s2, s3;
        unpack2(aA0, x, y); s0 = x + y;
        unpack2(aA1, x, y); s1 = x + y;
        unpack2(aB0, x, y); s2 = x + y;
        unpack2(aB1, x, y); s3 = x + y;

        // ---- butterfly reduce across the 8 kc lanes (bits 0..2) ----
        #pragma unroll
        for (int m = 1; m < 8; m <<= 1) {
            s0 += __shfl_xor_sync(0xffffffffu, s0, m);
            s1 += __shfl_xor_sync(0xffffffffu, s1, m);
            s2 += __shfl_xor_sync(0xffffffffu, s2, m);
            s3 += __shfl_xor_sync(0xffffffffu, s3, m);
        }

        if (pusher) {
            float a = (kc == 0) ? s0 : s2;
            float b = (kc == 0) ? s1 : s3;
            float v0 = fmaxf(z_cur.x + a, 0.f);
            float v1 = fmaxf(z_cur.y + b, 0.f);
            if (t < S_LEN - 1) {
                ull pv = pack2(v0, v1);
                int nxt = cur ^ 1;
                uint32_t dsel = nxt ? dd : 0u;
                uint32_t msel = nxt ? md1 : md0;
                #pragma unroll
                for (int r = 0; r < CL; r++)
                    st_async64(rb[r] + dsel, pv, rb[r] + msel);
            }
            *(float2*)(out + zoff) = make_float2(v0, v1);   // h_t overwrites z_t
            if (t == S_LEN - 1)
                *(float2*)(out + foff) = make_float2(v0, v1);
            z_cur = z_next;
            zoff += HDIM;
        }
        cur ^= 1;
    }
}

// =====================================================================
extern "C" void kernel_launch(void* const* d_in, const int* in_sizes, int n_in,
                              void* d_out, int out_size) {
    (void)in_sizes; (void)n_in; (void)out_size;
    const float* inputs = (const float*)d_in[0];
    const float* h0     = (const float*)d_in[1];
    const float* Wih    = (const float*)d_in[2];
    const float* Whh    = (const float*)d_in[3];
    const float* bih    = (const float*)d_in[4];
    const float* bhh    = (const float*)d_in[5];
    float* out = (float*)d_out;

    dim3 g1((BATCH * S_LEN) / BM, HDIM / BN);
    zproj_kernel<<<g1, 256>>>(inputs, Wih, bih, bhh, out);
    rnn_scan_kernel<<<(BATCH / 2) * CL, THREADS_R>>>(Whh, h0, out);
}